// round 3
// baseline (speedup 1.0000x reference)
#include <cuda_runtime.h>
#include <cstdint>

#define NN 50000
#define KD 512
#define EM 128
#define OD 64
#define EE 1600000           // max edges (fixed by problem)

// ---------------- scratch (device globals: no allocation allowed) ----------------
__device__ float g_h[(size_t)NN * EM];   // hidden after dense+lrelu
__device__ float g_g[(size_t)NN * OD];   // g = h @ Wg^T
__device__ float g_as[NN];               // a_src per node
__device__ float g_ad[NN];               // a_dst per node
__device__ int   g_cnt[NN];              // per-dst degree (incl. self loop)
__device__ int   g_off[NN];              // CSR offsets
__device__ int   g_pos[NN];              // scatter cursors
__device__ int   g_esrc[EE + NN];        // dst-bucketed src ids (slot 0 = self)

// ---------------- CSR build step 1: cnt = 1 (self loop) ----------------
__global__ void k_cnt_init() {
    int i = blockIdx.x * blockDim.x + threadIdx.x;
    if (i < NN) g_cnt[i] = 1;
}

// ---------------- CSR build step 2: histogram of dst ----------------
__global__ void k_hist(const int* __restrict__ ei, int E) {
    int i = blockIdx.x * blockDim.x + threadIdx.x;
    if (i < E) atomicAdd(g_cnt + ei[E + i], 1);
}

// ---------------- CSR build step 3: prefix scan + offsets + self entries ----------------
// single block, 1024 threads, 49 nodes per thread (1024*49 >= 50000)
__global__ __launch_bounds__(1024) void k_scan() {
    __shared__ int tsum[1024];
    const int CH = 49;
    int t = threadIdx.x;
    int beg = t * CH;
    int end = min(beg + CH, NN);
    int s = 0;
    for (int i = beg; i < end; i++) s += g_cnt[i];
    tsum[t] = s;
    __syncthreads();
    // Hillis–Steele inclusive scan
    for (int off = 1; off < 1024; off <<= 1) {
        int v = tsum[t];
        int u = (t >= off) ? tsum[t - off] : 0;
        __syncthreads();
        tsum[t] = v + u;
        __syncthreads();
    }
    int run = (t == 0) ? 0 : tsum[t - 1];
    for (int i = beg; i < end; i++) {
        g_off[i]     = run;
        g_pos[i]     = run + 1;   // slot 0 reserved for self loop
        g_esrc[run]  = i;         // self loop entry
        run += g_cnt[i];
    }
}

// ---------------- CSR build step 4: scatter edges into dst buckets ----------------
__global__ void k_scatter(const int* __restrict__ ei, int E) {
    int i = blockIdx.x * blockDim.x + threadIdx.x;
    if (i >= E) return;
    int s = ei[i];
    int d = ei[E + i];
    int p = atomicAdd(g_pos + d, 1);
    g_esrc[p] = s;
}

// ---------------- GEMM1: H = lrelu(X @ Wd^T + bd, 0.01) ----------------
#define BM 64
#define BN 128
#define BK 32
__global__ __launch_bounds__(256) void k_gemm1(const float* __restrict__ X,
                                               const float* __restrict__ Wd,
                                               const float* __restrict__ bd) {
    __shared__ float As[BK][BM + 4];
    __shared__ float Bs[BK][BN + 4];
    const int tid = threadIdx.x;
    const int tx = tid & 15;
    const int ty = tid >> 4;
    const int row0 = blockIdx.x * BM;

    float acc[4][8];
#pragma unroll
    for (int i = 0; i < 4; i++)
#pragma unroll
        for (int j = 0; j < 8; j++) acc[i][j] = 0.f;

    for (int k0 = 0; k0 < KD; k0 += BK) {
#pragma unroll
        for (int i = 0; i < 2; i++) {
            int f = tid + i * 256;
            int r = f >> 3;
            int kq = f & 7;
            float4 v = make_float4(0.f, 0.f, 0.f, 0.f);
            int rg = row0 + r;
            if (rg < NN)
                v = *reinterpret_cast<const float4*>(X + (size_t)rg * KD + k0 + kq * 4);
            As[kq * 4 + 0][r] = v.x; As[kq * 4 + 1][r] = v.y;
            As[kq * 4 + 2][r] = v.z; As[kq * 4 + 3][r] = v.w;
        }
#pragma unroll
        for (int i = 0; i < 4; i++) {
            int f = tid + i * 256;
            int c = f >> 3;
            int kq = f & 7;
            float4 v = *reinterpret_cast<const float4*>(Wd + (size_t)c * KD + k0 + kq * 4);
            Bs[kq * 4 + 0][c] = v.x; Bs[kq * 4 + 1][c] = v.y;
            Bs[kq * 4 + 2][c] = v.z; Bs[kq * 4 + 3][c] = v.w;
        }
        __syncthreads();
#pragma unroll
        for (int kk = 0; kk < BK; kk++) {
            float4 a  = *reinterpret_cast<const float4*>(&As[kk][ty * 4]);
            float4 b0 = *reinterpret_cast<const float4*>(&Bs[kk][tx * 8]);
            float4 b1 = *reinterpret_cast<const float4*>(&Bs[kk][tx * 8 + 4]);
            float av[4] = {a.x, a.y, a.z, a.w};
            float bv[8] = {b0.x, b0.y, b0.z, b0.w, b1.x, b1.y, b1.z, b1.w};
#pragma unroll
            for (int i = 0; i < 4; i++)
#pragma unroll
                for (int j = 0; j < 8; j++) acc[i][j] = fmaf(av[i], bv[j], acc[i][j]);
        }
        __syncthreads();
    }
#pragma unroll
    for (int i = 0; i < 4; i++) {
        int r = row0 + ty * 4 + i;
        if (r >= NN) continue;
#pragma unroll
        for (int j = 0; j < 8; j++) {
            int c = tx * 8 + j;
            float v = acc[i][j] + __ldg(bd + c);
            v = v > 0.f ? v : 0.01f * v;
            g_h[(size_t)r * EM + c] = v;
        }
    }
}

// ---------------- GEMM2 + attention logits ----------------
#define RPB 128
__global__ __launch_bounds__(256) void k_gemm2(const float* __restrict__ Wg,
                                               const float* __restrict__ att_s,
                                               const float* __restrict__ att_d) {
    __shared__ float Wgs[OD][EM + 4];
    __shared__ float hs[4][EM];
    __shared__ float red_s[4][2], red_d[4][2];
    __shared__ float ats[OD], atd[OD];
    const int tid = threadIdx.x;
    const int tx = tid & 63;
    const int ty = tid >> 6;

#pragma unroll
    for (int i = 0; i < 8; i++) {
        int f = tid + i * 256;
        int c = f >> 5;
        int kq = f & 31;
        float4 v = *reinterpret_cast<const float4*>(Wg + (size_t)c * EM + kq * 4);
        *reinterpret_cast<float4*>(&Wgs[c][kq * 4]) = v;
    }
    if (tid < OD) { ats[tid] = att_s[tid]; atd[tid] = att_d[tid]; }

    const int base = blockIdx.x * RPB;
    for (int rg = 0; rg < RPB; rg += 4) {
        __syncthreads();
        if (tid < 128) {
            int r = tid >> 5;
            int kq = tid & 31;
            int row = base + rg + r;
            float4 v = make_float4(0.f, 0.f, 0.f, 0.f);
            if (row < NN)
                v = *reinterpret_cast<const float4*>(g_h + (size_t)row * EM + kq * 4);
            *reinterpret_cast<float4*>(&hs[r][kq * 4]) = v;
        }
        __syncthreads();
        int row = base + rg + ty;
        float acc = 0.f;
#pragma unroll
        for (int k = 0; k < EM; k += 4) {
            float4 w  = *reinterpret_cast<const float4*>(&Wgs[tx][k]);
            float4 h4 = *reinterpret_cast<const float4*>(&hs[ty][k]);
            acc = fmaf(w.x, h4.x, acc);
            acc = fmaf(w.y, h4.y, acc);
            acc = fmaf(w.z, h4.z, acc);
            acc = fmaf(w.w, h4.w, acc);
        }
        if (row < NN) g_g[(size_t)row * OD + tx] = acc;

        float ps = acc * ats[tx];
        float pd = acc * atd[tx];
#pragma unroll
        for (int off = 16; off > 0; off >>= 1) {
            ps += __shfl_xor_sync(0xffffffffu, ps, off);
            pd += __shfl_xor_sync(0xffffffffu, pd, off);
        }
        int half = tx >> 5;
        if ((tx & 31) == 0) { red_s[ty][half] = ps; red_d[ty][half] = pd; }
        __syncthreads();
        if (tx == 0 && row < NN) {
            g_as[row] = red_s[ty][0] + red_s[ty][1];
            g_ad[row] = red_d[ty][0] + red_d[ty][1];
        }
    }
}

// ---------------- fused per-dst softmax + weighted gather (warp per dst) ----------------
__global__ __launch_bounds__(256) void k_accum(float* __restrict__ out,
                                               const float* __restrict__ bg) {
    int w    = (blockIdx.x * blockDim.x + threadIdx.x) >> 5;
    int lane = threadIdx.x & 31;
    if (w >= NN) return;
    int beg = g_off[w];
    int cnt = g_cnt[w];
    float a_d = g_ad[w];

    // pass 1: segment max (lanes stride edges, scalar gathers of g_as)
    float m = __int_as_float(0xff800000);
    for (int j = beg + lane; j < beg + cnt; j += 32) {
        int s = g_esrc[j];
        float e = g_as[s] + a_d;
        e = e > 0.f ? e : 0.2f * e;
        m = fmaxf(m, e);
    }
#pragma unroll
    for (int o = 16; o > 0; o >>= 1)
        m = fmaxf(m, __shfl_xor_sync(0xffffffffu, m, o));

    // pass 2: exp weights + register accumulation (float2 per lane = 64 cols)
    float den = 0.f, acc0 = 0.f, acc1 = 0.f;
    for (int j = beg; j < beg + cnt; j++) {
        int s = g_esrc[j];                       // same addr all lanes -> broadcast
        float e = g_as[s] + a_d;
        e = e > 0.f ? e : 0.2f * e;
        float wt = __expf(e - m);
        den += wt;
        float2 gv = *reinterpret_cast<const float2*>(g_g + (size_t)s * OD + lane * 2);
        acc0 = fmaf(wt, gv.x, acc0);
        acc1 = fmaf(wt, gv.y, acc1);
    }
    float inv = 1.f / den;
    out[(size_t)w * OD + lane * 2]     = acc0 * inv + __ldg(bg + lane * 2);
    out[(size_t)w * OD + lane * 2 + 1] = acc1 * inv + __ldg(bg + lane * 2 + 1);
}

// ---------------- launch ----------------
extern "C" void kernel_launch(void* const* d_in, const int* in_sizes, int n_in,
                              void* d_out, int out_size) {
    const float* x   = (const float*)d_in[0];
    const int*   ei  = (const int*)  d_in[1];
    const float* Wd  = (const float*)d_in[2];
    const float* bd  = (const float*)d_in[3];
    const float* Wg  = (const float*)d_in[4];
    const float* ats = (const float*)d_in[5];
    const float* atd = (const float*)d_in[6];
    const float* bg  = (const float*)d_in[7];
    float* out = (float*)d_out;

    const int E = in_sizes[1] / 2;

    // CSR build (independent of GEMMs)
    k_cnt_init<<<(NN + 255) / 256, 256>>>();
    k_hist<<<(E + 255) / 256, 256>>>(ei, E);
    k_scan<<<1, 1024>>>();
    k_scatter<<<(E + 255) / 256, 256>>>(ei, E);

    // dense pipeline
    k_gemm1<<<(NN + BM - 1) / BM, 256>>>(x, Wd, bd);
    k_gemm2<<<(NN + RPB - 1) / RPB, 256>>>(Wg, ats, atd);

    // fused softmax-gather, no atomics, writes final output
    k_accum<<<(NN * 32 + 255) / 256, 256>>>(out, bg);
}

// round 4
// speedup vs baseline: 1.8104x; 1.8104x over previous
#include <cuda_runtime.h>
#include <cstdint>

#define NN 50000
#define KD 512
#define EM 128
#define OD 64

// ---------------- scratch (device globals) ----------------
__device__ float g_h[(size_t)NN * EM];
__device__ float g_g[(size_t)NN * OD];
__device__ float g_as[NN];
__device__ float g_ad[NN];
__device__ float g_m[NN];
__device__ float g_den[NN];

__device__ __forceinline__ float to_tf32(float x) {
    float r;
    asm("cvt.rna.tf32.f32 %0, %1;" : "=f"(r) : "f"(x));
    return r;
}

// ---------------- init ----------------
__global__ void k_init(float* __restrict__ out) {
    int i = blockIdx.x * blockDim.x + threadIdx.x;
    if (i < NN) {
        g_m[i]   = __int_as_float(0xff800000);
        g_den[i] = 0.f;
    }
    if (i < NN * OD) out[i] = 0.f;
}

// ---------------- GEMM1 (tensor cores, tf32 mma.m16n8k8) ----------------
// H = lrelu(X[NN,512] @ Wd[128,512]^T + bd).  Block tile 128x128, BK=32.
// 8 warps: 2 (M) x 4 (N); warp tile 64x32 -> 4 m-tiles x 4 n-tiles of m16n8k8.
#define G1_BM 128
#define G1_BK 32
#define G1_LDS (G1_BK + 4)
__global__ __launch_bounds__(256) void k_gemm1(const float* __restrict__ X,
                                               const float* __restrict__ Wd,
                                               const float* __restrict__ bd) {
    __shared__ float As[G1_BM][G1_LDS];   // [row][k]
    __shared__ float Bs[EM][G1_LDS];      // [col][k]  (Wd natural layout)
    const int tid  = threadIdx.x;
    const int warp = tid >> 5;
    const int lane = tid & 31;
    const int g    = lane >> 2;        // groupID 0..7
    const int tig  = lane & 3;         // thread-in-group 0..3
    const int wm   = warp >> 2;        // 0..1  -> M offset wm*64
    const int wn   = warp & 3;         // 0..3  -> N offset wn*32
    const int row0 = blockIdx.x * G1_BM;

    float acc[4][4][4];
#pragma unroll
    for (int i = 0; i < 4; i++)
#pragma unroll
        for (int j = 0; j < 4; j++)
#pragma unroll
            for (int r = 0; r < 4; r++) acc[i][j][r] = 0.f;

    for (int k0 = 0; k0 < KD; k0 += G1_BK) {
        // A tile: 128 rows x 32 k = 1024 float4, 4 per thread
#pragma unroll
        for (int i = 0; i < 4; i++) {
            int f  = tid + i * 256;
            int r  = f >> 3;
            int kq = f & 7;
            float4 v = make_float4(0.f, 0.f, 0.f, 0.f);
            int rg = row0 + r;
            if (rg < NN)
                v = *reinterpret_cast<const float4*>(X + (size_t)rg * KD + k0 + kq * 4);
            v.x = to_tf32(v.x); v.y = to_tf32(v.y);
            v.z = to_tf32(v.z); v.w = to_tf32(v.w);
            *reinterpret_cast<float4*>(&As[r][kq * 4]) = v;
        }
        // B tile: 128 cols x 32 k
#pragma unroll
        for (int i = 0; i < 4; i++) {
            int f  = tid + i * 256;
            int c  = f >> 3;
            int kq = f & 7;
            float4 v = *reinterpret_cast<const float4*>(Wd + (size_t)c * KD + k0 + kq * 4);
            v.x = to_tf32(v.x); v.y = to_tf32(v.y);
            v.z = to_tf32(v.z); v.w = to_tf32(v.w);
            *reinterpret_cast<float4*>(&Bs[c][kq * 4]) = v;
        }
        __syncthreads();
#pragma unroll
        for (int ks = 0; ks < 4; ks++) {
            const int kb = ks * 8;
            // A fragments: 4 m-tiles
            uint32_t af[4][4];
#pragma unroll
            for (int mt = 0; mt < 4; mt++) {
                int ra = wm * 64 + mt * 16 + g;
                af[mt][0] = __float_as_uint(As[ra][kb + tig]);
                af[mt][1] = __float_as_uint(As[ra + 8][kb + tig]);
                af[mt][2] = __float_as_uint(As[ra][kb + tig + 4]);
                af[mt][3] = __float_as_uint(As[ra + 8][kb + tig + 4]);
            }
            // B fragments: 4 n-tiles
            uint32_t bf[4][2];
#pragma unroll
            for (int nt = 0; nt < 4; nt++) {
                int nb = wn * 32 + nt * 8 + g;
                bf[nt][0] = __float_as_uint(Bs[nb][kb + tig]);
                bf[nt][1] = __float_as_uint(Bs[nb][kb + tig + 4]);
            }
#pragma unroll
            for (int mt = 0; mt < 4; mt++)
#pragma unroll
                for (int nt = 0; nt < 4; nt++) {
                    asm volatile(
                        "mma.sync.aligned.m16n8k8.row.col.f32.tf32.tf32.f32 "
                        "{%0,%1,%2,%3}, {%4,%5,%6,%7}, {%8,%9}, {%0,%1,%2,%3};"
                        : "+f"(acc[mt][nt][0]), "+f"(acc[mt][nt][1]),
                          "+f"(acc[mt][nt][2]), "+f"(acc[mt][nt][3])
                        : "r"(af[mt][0]), "r"(af[mt][1]), "r"(af[mt][2]), "r"(af[mt][3]),
                          "r"(bf[nt][0]), "r"(bf[nt][1]));
                }
        }
        __syncthreads();
    }
    // epilogue: bias + leaky relu(0.01), float2 stores
#pragma unroll
    for (int mt = 0; mt < 4; mt++) {
#pragma unroll
        for (int half = 0; half < 2; half++) {
            int r = row0 + wm * 64 + mt * 16 + g + half * 8;
            if (r >= NN) continue;
#pragma unroll
            for (int nt = 0; nt < 4; nt++) {
                int c = wn * 32 + nt * 8 + tig * 2;
                float v0 = acc[mt][nt][half * 2]     + __ldg(bd + c);
                float v1 = acc[mt][nt][half * 2 + 1] + __ldg(bd + c + 1);
                v0 = v0 > 0.f ? v0 : 0.01f * v0;
                v1 = v1 > 0.f ? v1 : 0.01f * v1;
                *reinterpret_cast<float2*>(g_h + (size_t)r * EM + c) = make_float2(v0, v1);
            }
        }
    }
}

// ---------------- GEMM2 + attention logits ----------------
#define RPB 128
__global__ __launch_bounds__(256) void k_gemm2(const float* __restrict__ Wg,
                                               const float* __restrict__ att_s,
                                               const float* __restrict__ att_d) {
    __shared__ float Wgs[OD][EM + 4];
    __shared__ float hs[4][EM];
    __shared__ float red_s[4][2], red_d[4][2];
    __shared__ float ats[OD], atd[OD];
    const int tid = threadIdx.x;
    const int tx = tid & 63;
    const int ty = tid >> 6;

#pragma unroll
    for (int i = 0; i < 8; i++) {
        int f = tid + i * 256;
        int c = f >> 5;
        int kq = f & 31;
        float4 v = *reinterpret_cast<const float4*>(Wg + (size_t)c * EM + kq * 4);
        *reinterpret_cast<float4*>(&Wgs[c][kq * 4]) = v;
    }
    if (tid < OD) { ats[tid] = att_s[tid]; atd[tid] = att_d[tid]; }

    const int base = blockIdx.x * RPB;
    for (int rg = 0; rg < RPB; rg += 4) {
        __syncthreads();
        if (tid < 128) {
            int r = tid >> 5;
            int kq = tid & 31;
            int row = base + rg + r;
            float4 v = make_float4(0.f, 0.f, 0.f, 0.f);
            if (row < NN)
                v = *reinterpret_cast<const float4*>(g_h + (size_t)row * EM + kq * 4);
            *reinterpret_cast<float4*>(&hs[r][kq * 4]) = v;
        }
        __syncthreads();
        int row = base + rg + ty;
        float acc = 0.f;
#pragma unroll
        for (int k = 0; k < EM; k += 4) {
            float4 w  = *reinterpret_cast<const float4*>(&Wgs[tx][k]);
            float4 h4 = *reinterpret_cast<const float4*>(&hs[ty][k]);
            acc = fmaf(w.x, h4.x, acc);
            acc = fmaf(w.y, h4.y, acc);
            acc = fmaf(w.z, h4.z, acc);
            acc = fmaf(w.w, h4.w, acc);
        }
        if (row < NN) g_g[(size_t)row * OD + tx] = acc;

        float ps = acc * ats[tx];
        float pd = acc * atd[tx];
#pragma unroll
        for (int off = 16; off > 0; off >>= 1) {
            ps += __shfl_xor_sync(0xffffffffu, ps, off);
            pd += __shfl_xor_sync(0xffffffffu, pd, off);
        }
        int half = tx >> 5;
        if ((tx & 31) == 0) { red_s[ty][half] = ps; red_d[ty][half] = pd; }
        __syncthreads();
        if (tx == 0 && row < NN) {
            g_as[row] = red_s[ty][0] + red_s[ty][1];
            g_ad[row] = red_d[ty][0] + red_d[ty][1];
        }
    }
}

// ---------------- edge pass 1: segment max over dst ----------------
__global__ void k_edge_max(const int* __restrict__ ei, int E) {
    int i = blockIdx.x * blockDim.x + threadIdx.x;
    int total = E + NN;
    if (i >= total) return;
    int s, d;
    if (i < E) { s = ei[i]; d = ei[E + i]; }
    else       { s = d = i - E; }
    float e = g_as[s] + g_ad[d];
    e = e > 0.f ? e : 0.2f * e;
    if ((__float_as_uint(e) >> 31) == 0)
        atomicMax(reinterpret_cast<int*>(g_m + d), __float_as_int(e));
    else
        atomicMin(reinterpret_cast<unsigned int*>(g_m + d), __float_as_uint(e));
}

// ---------------- edge pass 2: weighted scatter ----------------
__global__ void k_edge_acc(const int* __restrict__ ei, int E, float* __restrict__ out) {
    int gid = blockIdx.x * blockDim.x + threadIdx.x;
    int edge = gid >> 4;
    int lane = gid & 15;
    int total = E + NN;
    if (edge >= total) return;
    int s, d;
    if (edge < E) { s = ei[edge]; d = ei[E + edge]; }
    else          { s = d = edge - E; }
    float e = g_as[s] + g_ad[d];
    e = e > 0.f ? e : 0.2f * e;
    float w = __expf(e - g_m[d]);
    if (lane == 0) atomicAdd(g_den + d, w);
    float4 v = *reinterpret_cast<const float4*>(g_g + (size_t)s * OD + lane * 4);
    v.x *= w; v.y *= w; v.z *= w; v.w *= w;
    float* p = out + (size_t)d * OD + lane * 4;
    asm volatile("red.global.add.v4.f32 [%0], {%1,%2,%3,%4};"
                 :: "l"(p), "f"(v.x), "f"(v.y), "f"(v.z), "f"(v.w)
                 : "memory");
}

// ---------------- finalize ----------------
__global__ void k_final(float* __restrict__ out, const float* __restrict__ bg) {
    int i = blockIdx.x * blockDim.x + threadIdx.x;
    if (i >= NN * OD) return;
    int d = i >> 6;
    int c = i & 63;
    out[i] = out[i] / g_den[d] + __ldg(bg + c);
}

// ---------------- launch ----------------
extern "C" void kernel_launch(void* const* d_in, const int* in_sizes, int n_in,
                              void* d_out, int out_size) {
    const float* x   = (const float*)d_in[0];
    const int*   ei  = (const int*)  d_in[1];
    const float* Wd  = (const float*)d_in[2];
    const float* bd  = (const float*)d_in[3];
    const float* Wg  = (const float*)d_in[4];
    const float* ats = (const float*)d_in[5];
    const float* atd = (const float*)d_in[6];
    const float* bg  = (const float*)d_in[7];
    float* out = (float*)d_out;

    const int E = in_sizes[1] / 2;
    const int total = E + NN;

    k_init<<<(NN * OD + 255) / 256, 256>>>(out);
    k_gemm1<<<(NN + G1_BM - 1) / G1_BM, 256>>>(x, Wd, bd);
    k_gemm2<<<(NN + RPB - 1) / RPB, 256>>>(Wg, ats, atd);
    k_edge_max<<<(total + 255) / 256, 256>>>(ei, E);
    {
        long long threads = (long long)total * 16;
        int blocks = (int)((threads + 255) / 256);
        k_edge_acc<<<blocks, 256>>>(ei, E, out);
    }
    k_final<<<(NN * OD + 255) / 256, 256>>>(out, bg);
}

// round 5
// speedup vs baseline: 1.9627x; 1.0841x over previous
#include <cuda_runtime.h>
#include <cstdint>

#define NN 50000
#define KD 512
#define EM 128
#define OD 64
#define EE 1600000

// ---------------- scratch (device globals) ----------------
__device__ float g_h[(size_t)NN * EM];
__device__ float g_g[(size_t)NN * OD];
__device__ float g_as[NN];
__device__ float g_ad[NN];
__device__ float g_den[NN];
__device__ float g_w[EE + NN];

__device__ __forceinline__ float to_tf32(float x) {
    float r;
    asm("cvt.rna.tf32.f32 %0, %1;" : "=f"(r) : "f"(x));
    return r;
}

// ---------------- init ----------------
__global__ void k_init(float* __restrict__ out) {
    int i = blockIdx.x * blockDim.x + threadIdx.x;
    if (i < NN) g_den[i] = 0.f;
    if (i < NN * OD) out[i] = 0.f;
}

// ---------------- GEMM1 (tensor cores, tf32 mma.m16n8k8) ----------------
#define G1_BM 128
#define G1_BK 32
#define G1_LDS (G1_BK + 4)
__global__ __launch_bounds__(256) void k_gemm1(const float* __restrict__ X,
                                               const float* __restrict__ Wd,
                                               const float* __restrict__ bd) {
    __shared__ float As[G1_BM][G1_LDS];
    __shared__ float Bs[EM][G1_LDS];
    const int tid  = threadIdx.x;
    const int warp = tid >> 5;
    const int lane = tid & 31;
    const int g    = lane >> 2;
    const int tig  = lane & 3;
    const int wm   = warp >> 2;
    const int wn   = warp & 3;
    const int row0 = blockIdx.x * G1_BM;

    float acc[4][4][4];
#pragma unroll
    for (int i = 0; i < 4; i++)
#pragma unroll
        for (int j = 0; j < 4; j++)
#pragma unroll
            for (int r = 0; r < 4; r++) acc[i][j][r] = 0.f;

    for (int k0 = 0; k0 < KD; k0 += G1_BK) {
#pragma unroll
        for (int i = 0; i < 4; i++) {
            int f  = tid + i * 256;
            int r  = f >> 3;
            int kq = f & 7;
            float4 v = make_float4(0.f, 0.f, 0.f, 0.f);
            int rg = row0 + r;
            if (rg < NN)
                v = *reinterpret_cast<const float4*>(X + (size_t)rg * KD + k0 + kq * 4);
            v.x = to_tf32(v.x); v.y = to_tf32(v.y);
            v.z = to_tf32(v.z); v.w = to_tf32(v.w);
            *reinterpret_cast<float4*>(&As[r][kq * 4]) = v;
        }
#pragma unroll
        for (int i = 0; i < 4; i++) {
            int f  = tid + i * 256;
            int c  = f >> 3;
            int kq = f & 7;
            float4 v = *reinterpret_cast<const float4*>(Wd + (size_t)c * KD + k0 + kq * 4);
            v.x = to_tf32(v.x); v.y = to_tf32(v.y);
            v.z = to_tf32(v.z); v.w = to_tf32(v.w);
            *reinterpret_cast<float4*>(&Bs[c][kq * 4]) = v;
        }
        __syncthreads();
#pragma unroll
        for (int ks = 0; ks < 4; ks++) {
            const int kb = ks * 8;
            uint32_t af[4][4];
#pragma unroll
            for (int mt = 0; mt < 4; mt++) {
                int ra = wm * 64 + mt * 16 + g;
                af[mt][0] = __float_as_uint(As[ra][kb + tig]);
                af[mt][1] = __float_as_uint(As[ra + 8][kb + tig]);
                af[mt][2] = __float_as_uint(As[ra][kb + tig + 4]);
                af[mt][3] = __float_as_uint(As[ra + 8][kb + tig + 4]);
            }
            uint32_t bf[4][2];
#pragma unroll
            for (int nt = 0; nt < 4; nt++) {
                int nb = wn * 32 + nt * 8 + g;
                bf[nt][0] = __float_as_uint(Bs[nb][kb + tig]);
                bf[nt][1] = __float_as_uint(Bs[nb][kb + tig + 4]);
            }
#pragma unroll
            for (int mt = 0; mt < 4; mt++)
#pragma unroll
                for (int nt = 0; nt < 4; nt++) {
                    asm volatile(
                        "mma.sync.aligned.m16n8k8.row.col.f32.tf32.tf32.f32 "
                        "{%0,%1,%2,%3}, {%4,%5,%6,%7}, {%8,%9}, {%0,%1,%2,%3};"
                        : "+f"(acc[mt][nt][0]), "+f"(acc[mt][nt][1]),
                          "+f"(acc[mt][nt][2]), "+f"(acc[mt][nt][3])
                        : "r"(af[mt][0]), "r"(af[mt][1]), "r"(af[mt][2]), "r"(af[mt][3]),
                          "r"(bf[nt][0]), "r"(bf[nt][1]));
                }
        }
        __syncthreads();
    }
#pragma unroll
    for (int mt = 0; mt < 4; mt++) {
#pragma unroll
        for (int half = 0; half < 2; half++) {
            int r = row0 + wm * 64 + mt * 16 + g + half * 8;
            if (r >= NN) continue;
#pragma unroll
            for (int nt = 0; nt < 4; nt++) {
                int c = wn * 32 + nt * 8 + tig * 2;
                float v0 = acc[mt][nt][half * 2]     + __ldg(bd + c);
                float v1 = acc[mt][nt][half * 2 + 1] + __ldg(bd + c + 1);
                v0 = v0 > 0.f ? v0 : 0.01f * v0;
                v1 = v1 > 0.f ? v1 : 0.01f * v1;
                *reinterpret_cast<float2*>(g_h + (size_t)r * EM + c) = make_float2(v0, v1);
            }
        }
    }
}

// ---------------- GEMM2 + attention logits ----------------
#define RPB 128
__global__ __launch_bounds__(256) void k_gemm2(const float* __restrict__ Wg,
                                               const float* __restrict__ att_s,
                                               const float* __restrict__ att_d) {
    __shared__ float Wgs[OD][EM + 4];
    __shared__ float hs[4][EM];
    __shared__ float red_s[4][2], red_d[4][2];
    __shared__ float ats[OD], atd[OD];
    const int tid = threadIdx.x;
    const int tx = tid & 63;
    const int ty = tid >> 6;

#pragma unroll
    for (int i = 0; i < 8; i++) {
        int f = tid + i * 256;
        int c = f >> 5;
        int kq = f & 31;
        float4 v = *reinterpret_cast<const float4*>(Wg + (size_t)c * EM + kq * 4);
        *reinterpret_cast<float4*>(&Wgs[c][kq * 4]) = v;
    }
    if (tid < OD) { ats[tid] = att_s[tid]; atd[tid] = att_d[tid]; }

    const int base = blockIdx.x * RPB;
    for (int rg = 0; rg < RPB; rg += 4) {
        __syncthreads();
        if (tid < 128) {
            int r = tid >> 5;
            int kq = tid & 31;
            int row = base + rg + r;
            float4 v = make_float4(0.f, 0.f, 0.f, 0.f);
            if (row < NN)
                v = *reinterpret_cast<const float4*>(g_h + (size_t)row * EM + kq * 4);
            *reinterpret_cast<float4*>(&hs[r][kq * 4]) = v;
        }
        __syncthreads();
        int row = base + rg + ty;
        float acc = 0.f;
#pragma unroll
        for (int k = 0; k < EM; k += 4) {
            float4 w  = *reinterpret_cast<const float4*>(&Wgs[tx][k]);
            float4 h4 = *reinterpret_cast<const float4*>(&hs[ty][k]);
            acc = fmaf(w.x, h4.x, acc);
            acc = fmaf(w.y, h4.y, acc);
            acc = fmaf(w.z, h4.z, acc);
            acc = fmaf(w.w, h4.w, acc);
        }
        if (row < NN) g_g[(size_t)row * OD + tx] = acc;

        float ps = acc * ats[tx];
        float pd = acc * atd[tx];
#pragma unroll
        for (int off = 16; off > 0; off >>= 1) {
            ps += __shfl_xor_sync(0xffffffffu, ps, off);
            pd += __shfl_xor_sync(0xffffffffu, pd, off);
        }
        int half = tx >> 5;
        if ((tx & 31) == 0) { red_s[ty][half] = ps; red_d[ty][half] = pd; }
        __syncthreads();
        if (tx == 0 && row < NN) {
            g_as[row] = red_s[ty][0] + red_s[ty][1];
            g_ad[row] = red_d[ty][0] + red_d[ty][1];
        }
    }
}

// ---------------- edge weights: w = exp(lrelu(a_src+a_dst)), denom accumulate ----------------
// Softmax shift-invariance: no max subtraction needed (logits are O(1) here,
// exp cannot overflow; result identical up to fp rounding).
__global__ void k_edge_w(const int* __restrict__ ei, int E) {
    int i = blockIdx.x * blockDim.x + threadIdx.x;
    int total = E + NN;
    if (i >= total) return;
    int s, d;
    if (i < E) { s = ei[i]; d = ei[E + i]; }
    else       { s = d = i - E; }
    float e = g_as[s] + g_ad[d];
    e = e > 0.f ? e : 0.2f * e;
    float w = __expf(e);
    g_w[i] = w;
    atomicAdd(g_den + d, w);
}

// ---------------- edge pass 2: weighted scatter (lean) ----------------
__global__ void k_edge_acc(const int* __restrict__ ei, int E, float* __restrict__ out) {
    int gid = blockIdx.x * blockDim.x + threadIdx.x;
    int edge = gid >> 4;
    int lane = gid & 15;
    int total = E + NN;
    if (edge >= total) return;
    int s, d;
    if (edge < E) { s = ei[edge]; d = ei[E + edge]; }
    else          { s = d = edge - E; }
    float w = g_w[edge];                      // broadcast within half-warps
    float4 v = *reinterpret_cast<const float4*>(g_g + (size_t)s * OD + lane * 4);
    v.x *= w; v.y *= w; v.z *= w; v.w *= w;
    float* p = out + (size_t)d * OD + lane * 4;
    asm volatile("red.global.add.v4.f32 [%0], {%1,%2,%3,%4};"
                 :: "l"(p), "f"(v.x), "f"(v.y), "f"(v.z), "f"(v.w)
                 : "memory");
}

// ---------------- finalize ----------------
__global__ void k_final(float* __restrict__ out, const float* __restrict__ bg) {
    int i = blockIdx.x * blockDim.x + threadIdx.x;
    if (i >= NN * OD) return;
    int d = i >> 6;
    int c = i & 63;
    out[i] = out[i] / g_den[d] + __ldg(bg + c);
}

// ---------------- launch ----------------
extern "C" void kernel_launch(void* const* d_in, const int* in_sizes, int n_in,
                              void* d_out, int out_size) {
    const float* x   = (const float*)d_in[0];
    const int*   ei  = (const int*)  d_in[1];
    const float* Wd  = (const float*)d_in[2];
    const float* bd  = (const float*)d_in[3];
    const float* Wg  = (const float*)d_in[4];
    const float* ats = (const float*)d_in[5];
    const float* atd = (const float*)d_in[6];
    const float* bg  = (const float*)d_in[7];
    float* out = (float*)d_out;

    const int E = in_sizes[1] / 2;
    const int total = E + NN;

    k_init<<<(NN * OD + 255) / 256, 256>>>(out);
    k_gemm1<<<(NN + G1_BM - 1) / G1_BM, 256>>>(x, Wd, bd);
    k_gemm2<<<(NN + RPB - 1) / RPB, 256>>>(Wg, ats, atd);
    k_edge_w<<<(total + 255) / 256, 256>>>(ei, E);
    {
        long long threads = (long long)total * 16;
        int blocks = (int)((threads + 255) / 256);
        k_edge_acc<<<blocks, 256>>>(ei, E, out);
    }
    k_final<<<(NN * OD + 255) / 256, 256>>>(out, bg);
}

// round 6
// speedup vs baseline: 2.1634x; 1.1022x over previous
#include <cuda_runtime.h>
#include <cstdint>

#define NN 50000
#define KD 512
#define EM 128
#define OD 64
#define EE 1600000
#define SCAN_B 196            // 196 * 256 = 50176 >= NN

// ---------------- scratch (device globals) ----------------
__device__ float g_h[(size_t)NN * EM];
__device__ float g_g[(size_t)NN * OD];
__device__ float g_as[NN];
__device__ float g_ad[NN];
__device__ int   g_cnt[NN];
__device__ int   g_off[NN];
__device__ int   g_pos[NN];
__device__ int   g_esrc[EE];
__device__ int   g_bsum[SCAN_B];
__device__ int   g_boff[SCAN_B];

__device__ __forceinline__ float to_tf32(float x) {
    float r;
    asm("cvt.rna.tf32.f32 %0, %1;" : "=f"(r) : "f"(x));
    return r;
}

// ---------------- CSR build ----------------
__global__ void k_zero() {
    int i = blockIdx.x * blockDim.x + threadIdx.x;
    if (i < NN) g_cnt[i] = 0;
}

__global__ void k_hist(const int* __restrict__ ei, int E) {
    int i = blockIdx.x * blockDim.x + threadIdx.x;
    if (i < E) atomicAdd(g_cnt + ei[E + i], 1);
}

// block partial sums
__global__ __launch_bounds__(256) void k_scan1() {
    __shared__ int sh[256];
    int t = threadIdx.x;
    int i = blockIdx.x * 256 + t;
    int v = (i < NN) ? g_cnt[i] : 0;
    sh[t] = v;
    __syncthreads();
#pragma unroll
    for (int o = 128; o > 0; o >>= 1) {
        if (t < o) sh[t] += sh[t + o];
        __syncthreads();
    }
    if (t == 0) g_bsum[blockIdx.x] = sh[0];
}

// exclusive scan of block sums (single block)
__global__ __launch_bounds__(256) void k_scan2() {
    __shared__ int sh[256];
    int t = threadIdx.x;
    int v = (t < SCAN_B) ? g_bsum[t] : 0;
    sh[t] = v;
    __syncthreads();
#pragma unroll
    for (int o = 1; o < 256; o <<= 1) {
        int u = (t >= o) ? sh[t - o] : 0;
        __syncthreads();
        sh[t] += u;
        __syncthreads();
    }
    if (t < SCAN_B) g_boff[t] = sh[t] - v;
}

// per-block exclusive scan + base offset
__global__ __launch_bounds__(256) void k_scan3() {
    __shared__ int sh[256];
    int t = threadIdx.x;
    int i = blockIdx.x * 256 + t;
    int v = (i < NN) ? g_cnt[i] : 0;
    sh[t] = v;
    __syncthreads();
#pragma unroll
    for (int o = 1; o < 256; o <<= 1) {
        int u = (t >= o) ? sh[t - o] : 0;
        __syncthreads();
        sh[t] += u;
        __syncthreads();
    }
    if (i < NN) {
        int off = g_boff[blockIdx.x] + sh[t] - v;
        g_off[i] = off;
        g_pos[i] = off;
    }
}

__global__ void k_scatter(const int* __restrict__ ei, int E) {
    int i = blockIdx.x * blockDim.x + threadIdx.x;
    if (i >= E) return;
    int s = ei[i];
    int d = ei[E + i];
    int p = atomicAdd(g_pos + d, 1);
    g_esrc[p] = s;
}

// ---------------- GEMM1 (tensor cores, tf32 mma.m16n8k8) ----------------
#define G1_BM 128
#define G1_BK 32
#define G1_LDS (G1_BK + 4)
__global__ __launch_bounds__(256) void k_gemm1(const float* __restrict__ X,
                                               const float* __restrict__ Wd,
                                               const float* __restrict__ bd) {
    __shared__ float As[G1_BM][G1_LDS];
    __shared__ float Bs[EM][G1_LDS];
    const int tid  = threadIdx.x;
    const int warp = tid >> 5;
    const int lane = tid & 31;
    const int g    = lane >> 2;
    const int tig  = lane & 3;
    const int wm   = warp >> 2;
    const int wn   = warp & 3;
    const int row0 = blockIdx.x * G1_BM;

    float acc[4][4][4];
#pragma unroll
    for (int i = 0; i < 4; i++)
#pragma unroll
        for (int j = 0; j < 4; j++)
#pragma unroll
            for (int r = 0; r < 4; r++) acc[i][j][r] = 0.f;

    for (int k0 = 0; k0 < KD; k0 += G1_BK) {
#pragma unroll
        for (int i = 0; i < 4; i++) {
            int f  = tid + i * 256;
            int r  = f >> 3;
            int kq = f & 7;
            float4 v = make_float4(0.f, 0.f, 0.f, 0.f);
            int rg = row0 + r;
            if (rg < NN)
                v = *reinterpret_cast<const float4*>(X + (size_t)rg * KD + k0 + kq * 4);
            v.x = to_tf32(v.x); v.y = to_tf32(v.y);
            v.z = to_tf32(v.z); v.w = to_tf32(v.w);
            *reinterpret_cast<float4*>(&As[r][kq * 4]) = v;
        }
#pragma unroll
        for (int i = 0; i < 4; i++) {
            int f  = tid + i * 256;
            int c  = f >> 3;
            int kq = f & 7;
            float4 v = *reinterpret_cast<const float4*>(Wd + (size_t)c * KD + k0 + kq * 4);
            v.x = to_tf32(v.x); v.y = to_tf32(v.y);
            v.z = to_tf32(v.z); v.w = to_tf32(v.w);
            *reinterpret_cast<float4*>(&Bs[c][kq * 4]) = v;
        }
        __syncthreads();
#pragma unroll
        for (int ks = 0; ks < 4; ks++) {
            const int kb = ks * 8;
            uint32_t af[4][4];
#pragma unroll
            for (int mt = 0; mt < 4; mt++) {
                int ra = wm * 64 + mt * 16 + g;
                af[mt][0] = __float_as_uint(As[ra][kb + tig]);
                af[mt][1] = __float_as_uint(As[ra + 8][kb + tig]);
                af[mt][2] = __float_as_uint(As[ra][kb + tig + 4]);
                af[mt][3] = __float_as_uint(As[ra + 8][kb + tig + 4]);
            }
            uint32_t bf[4][2];
#pragma unroll
            for (int nt = 0; nt < 4; nt++) {
                int nb = wn * 32 + nt * 8 + g;
                bf[nt][0] = __float_as_uint(Bs[nb][kb + tig]);
                bf[nt][1] = __float_as_uint(Bs[nb][kb + tig + 4]);
            }
#pragma unroll
            for (int mt = 0; mt < 4; mt++)
#pragma unroll
                for (int nt = 0; nt < 4; nt++) {
                    asm volatile(
                        "mma.sync.aligned.m16n8k8.row.col.f32.tf32.tf32.f32 "
                        "{%0,%1,%2,%3}, {%4,%5,%6,%7}, {%8,%9}, {%0,%1,%2,%3};"
                        : "+f"(acc[mt][nt][0]), "+f"(acc[mt][nt][1]),
                          "+f"(acc[mt][nt][2]), "+f"(acc[mt][nt][3])
                        : "r"(af[mt][0]), "r"(af[mt][1]), "r"(af[mt][2]), "r"(af[mt][3]),
                          "r"(bf[nt][0]), "r"(bf[nt][1]));
                }
        }
        __syncthreads();
    }
#pragma unroll
    for (int mt = 0; mt < 4; mt++) {
#pragma unroll
        for (int half = 0; half < 2; half++) {
            int r = row0 + wm * 64 + mt * 16 + g + half * 8;
            if (r >= NN) continue;
#pragma unroll
            for (int nt = 0; nt < 4; nt++) {
                int c = wn * 32 + nt * 8 + tig * 2;
                float v0 = acc[mt][nt][half * 2]     + __ldg(bd + c);
                float v1 = acc[mt][nt][half * 2 + 1] + __ldg(bd + c + 1);
                v0 = v0 > 0.f ? v0 : 0.01f * v0;
                v1 = v1 > 0.f ? v1 : 0.01f * v1;
                *reinterpret_cast<float2*>(g_h + (size_t)r * EM + c) = make_float2(v0, v1);
            }
        }
    }
}

// ---------------- GEMM2 + attention logits ----------------
#define RPB 128
__global__ __launch_bounds__(256) void k_gemm2(const float* __restrict__ Wg,
                                               const float* __restrict__ att_s,
                                               const float* __restrict__ att_d) {
    __shared__ float Wgs[OD][EM + 4];
    __shared__ float hs[4][EM];
    __shared__ float red_s[4][2], red_d[4][2];
    __shared__ float ats[OD], atd[OD];
    const int tid = threadIdx.x;
    const int tx = tid & 63;
    const int ty = tid >> 6;

#pragma unroll
    for (int i = 0; i < 8; i++) {
        int f = tid + i * 256;
        int c = f >> 5;
        int kq = f & 31;
        float4 v = *reinterpret_cast<const float4*>(Wg + (size_t)c * EM + kq * 4);
        *reinterpret_cast<float4*>(&Wgs[c][kq * 4]) = v;
    }
    if (tid < OD) { ats[tid] = att_s[tid]; atd[tid] = att_d[tid]; }

    const int base = blockIdx.x * RPB;
    for (int rg = 0; rg < RPB; rg += 4) {
        __syncthreads();
        if (tid < 128) {
            int r = tid >> 5;
            int kq = tid & 31;
            int row = base + rg + r;
            float4 v = make_float4(0.f, 0.f, 0.f, 0.f);
            if (row < NN)
                v = *reinterpret_cast<const float4*>(g_h + (size_t)row * EM + kq * 4);
            *reinterpret_cast<float4*>(&hs[r][kq * 4]) = v;
        }
        __syncthreads();
        int row = base + rg + ty;
        float acc = 0.f;
#pragma unroll
        for (int k = 0; k < EM; k += 4) {
            float4 w  = *reinterpret_cast<const float4*>(&Wgs[tx][k]);
            float4 h4 = *reinterpret_cast<const float4*>(&hs[ty][k]);
            acc = fmaf(w.x, h4.x, acc);
            acc = fmaf(w.y, h4.y, acc);
            acc = fmaf(w.z, h4.z, acc);
            acc = fmaf(w.w, h4.w, acc);
        }
        if (row < NN) g_g[(size_t)row * OD + tx] = acc;

        float ps = acc * ats[tx];
        float pd = acc * atd[tx];
#pragma unroll
        for (int off = 16; off > 0; off >>= 1) {
            ps += __shfl_xor_sync(0xffffffffu, ps, off);
            pd += __shfl_xor_sync(0xffffffffu, pd, off);
        }
        int half = tx >> 5;
        if ((tx & 31) == 0) { red_s[ty][half] = ps; red_d[ty][half] = pd; }
        __syncthreads();
        if (tx == 0 && row < NN) {
            g_as[row] = red_s[ty][0] + red_s[ty][1];
            g_ad[row] = red_d[ty][0] + red_d[ty][1];
        }
    }
}

// ---------------- fused softmax + gather accumulate (warp per dst, no atomics) ----------------
// w = exp(lrelu(a_src+a_dst, 0.2)); softmax shift-invariance: logits O(1), no max needed.
__global__ __launch_bounds__(256) void k_accum(float* __restrict__ out,
                                               const float* __restrict__ bg) {
    const unsigned FULL = 0xffffffffu;
    int w    = (blockIdx.x * blockDim.x + threadIdx.x) >> 5;
    int lane = threadIdx.x & 31;
    if (w >= NN) return;
    int beg = g_off[w];
    int cnt = g_cnt[w];
    float a_d = g_ad[w];

    // self loop (appended in reference; order within segment is fp-irrelevant)
    float e0 = g_as[w] + a_d;
    e0 = e0 > 0.f ? e0 : 0.2f * e0;
    float den = __expf(e0);
    float2 gw = *reinterpret_cast<const float2*>(g_g + (size_t)w * OD + lane * 2);
    float acc0 = den * gw.x, acc1 = den * gw.y;

    int j = beg, end = beg + cnt;
    // 8 edges per group: lanes 0..7 load src + a_src, broadcast, 8 MLP gathers
    for (; j + 8 <= end; j += 8) {
        int   s_l = 0;
        float a_l = 0.f;
        if (lane < 8) {
            s_l = g_esrc[j + lane];
            a_l = g_as[s_l];
        }
#pragma unroll
        for (int u = 0; u < 8; u++) {
            int   s  = __shfl_sync(FULL, s_l, u);
            float as = __shfl_sync(FULL, a_l, u);
            float e  = as + a_d;
            e = e > 0.f ? e : 0.2f * e;
            float wt = __expf(e);
            den += wt;
            float2 gv = *reinterpret_cast<const float2*>(g_g + (size_t)s * OD + lane * 2);
            acc0 = fmaf(wt, gv.x, acc0);
            acc1 = fmaf(wt, gv.y, acc1);
        }
    }
    // tail
    for (; j < end; j++) {
        int s = g_esrc[j];
        float e = g_as[s] + a_d;
        e = e > 0.f ? e : 0.2f * e;
        float wt = __expf(e);
        den += wt;
        float2 gv = *reinterpret_cast<const float2*>(g_g + (size_t)s * OD + lane * 2);
        acc0 = fmaf(wt, gv.x, acc0);
        acc1 = fmaf(wt, gv.y, acc1);
    }
    float inv = 1.f / den;
    int c = lane * 2;
    out[(size_t)w * OD + c]     = acc0 * inv + __ldg(bg + c);
    out[(size_t)w * OD + c + 1] = acc1 * inv + __ldg(bg + c + 1);
}

// ---------------- launch ----------------
extern "C" void kernel_launch(void* const* d_in, const int* in_sizes, int n_in,
                              void* d_out, int out_size) {
    const float* x   = (const float*)d_in[0];
    const int*   ei  = (const int*)  d_in[1];
    const float* Wd  = (const float*)d_in[2];
    const float* bd  = (const float*)d_in[3];
    const float* Wg  = (const float*)d_in[4];
    const float* ats = (const float*)d_in[5];
    const float* atd = (const float*)d_in[6];
    const float* bg  = (const float*)d_in[7];
    float* out = (float*)d_out;

    const int E = in_sizes[1] / 2;

    // CSR build (independent of GEMMs)
    k_zero<<<(NN + 255) / 256, 256>>>();
    k_hist<<<(E + 255) / 256, 256>>>(ei, E);
    k_scan1<<<SCAN_B, 256>>>();
    k_scan2<<<1, 256>>>();
    k_scan3<<<SCAN_B, 256>>>();
    k_scatter<<<(E + 255) / 256, 256>>>(ei, E);

    // dense pipeline
    k_gemm1<<<(NN + G1_BM - 1) / G1_BM, 256>>>(x, Wd, bd);
    k_gemm2<<<(NN + RPB - 1) / RPB, 256>>>(Wg, ats, atd);

    // fused softmax-gather-normalize, writes final output
    k_accum<<<(NN * 32 + 255) / 256, 256>>>(out, bg);
}

// round 7
// speedup vs baseline: 2.4121x; 1.1150x over previous
#include <cuda_runtime.h>
#include <cstdint>

#define NN 50000
#define KD 512
#define EM 128
#define OD 64
#define EE 1600000
#define SCAN_B 196            // 196 * 256 = 50176 >= NN

// ---------------- scratch (device globals) ----------------
__device__ float g_h[(size_t)NN * EM];
__device__ float g_g[(size_t)NN * OD];
__device__ float g_as[NN];
__device__ float g_ad[NN];
__device__ int   g_cnt[NN];
__device__ int   g_off[NN];
__device__ int   g_pos[NN];
__device__ int   g_esrc[EE];
__device__ int   g_bsum[SCAN_B];
__device__ int   g_boff[SCAN_B];

__device__ __forceinline__ float to_tf32(float x) {
    float r;
    asm("cvt.rna.tf32.f32 %0, %1;" : "=f"(r) : "f"(x));
    return r;
}

// ---------------- CSR build ----------------
__global__ void k_zero() {
    int i = blockIdx.x * blockDim.x + threadIdx.x;
    if (i < NN) g_cnt[i] = 0;
}

__global__ void k_hist(const int* __restrict__ ei, int E) {
    int i = blockIdx.x * blockDim.x + threadIdx.x;
    if (i < E) atomicAdd(g_cnt + ei[E + i], 1);
}

__global__ __launch_bounds__(256) void k_scan1() {
    __shared__ int sh[256];
    int t = threadIdx.x;
    int i = blockIdx.x * 256 + t;
    int v = (i < NN) ? g_cnt[i] : 0;
    sh[t] = v;
    __syncthreads();
#pragma unroll
    for (int o = 128; o > 0; o >>= 1) {
        if (t < o) sh[t] += sh[t + o];
        __syncthreads();
    }
    if (t == 0) g_bsum[blockIdx.x] = sh[0];
}

__global__ __launch_bounds__(256) void k_scan2() {
    __shared__ int sh[256];
    int t = threadIdx.x;
    int v = (t < SCAN_B) ? g_bsum[t] : 0;
    sh[t] = v;
    __syncthreads();
#pragma unroll
    for (int o = 1; o < 256; o <<= 1) {
        int u = (t >= o) ? sh[t - o] : 0;
        __syncthreads();
        sh[t] += u;
        __syncthreads();
    }
    if (t < SCAN_B) g_boff[t] = sh[t] - v;
}

__global__ __launch_bounds__(256) void k_scan3() {
    __shared__ int sh[256];
    int t = threadIdx.x;
    int i = blockIdx.x * 256 + t;
    int v = (i < NN) ? g_cnt[i] : 0;
    sh[t] = v;
    __syncthreads();
#pragma unroll
    for (int o = 1; o < 256; o <<= 1) {
        int u = (t >= o) ? sh[t - o] : 0;
        __syncthreads();
        sh[t] += u;
        __syncthreads();
    }
    if (i < NN) {
        int off = g_boff[blockIdx.x] + sh[t] - v;
        g_off[i] = off;
        g_pos[i] = off;
    }
}

__global__ void k_scatter(const int* __restrict__ ei, int E) {
    int i = blockIdx.x * blockDim.x + threadIdx.x;
    if (i >= E) return;
    int s = ei[i];
    int d = ei[E + i];
    int p = atomicAdd(g_pos + d, 1);
    g_esrc[p] = s;
}

// ---------------- GEMM1 (tensor cores, tf32 mma.m16n8k8) ----------------
#define G1_BM 128
#define G1_BK 32
#define G1_LDS (G1_BK + 4)
__global__ __launch_bounds__(256) void k_gemm1(const float* __restrict__ X,
                                               const float* __restrict__ Wd,
                                               const float* __restrict__ bd) {
    __shared__ float As[G1_BM][G1_LDS];
    __shared__ float Bs[EM][G1_LDS];
    const int tid  = threadIdx.x;
    const int warp = tid >> 5;
    const int lane = tid & 31;
    const int g    = lane >> 2;
    const int tig  = lane & 3;
    const int wm   = warp >> 2;
    const int wn   = warp & 3;
    const int row0 = blockIdx.x * G1_BM;

    float acc[4][4][4];
#pragma unroll
    for (int i = 0; i < 4; i++)
#pragma unroll
        for (int j = 0; j < 4; j++)
#pragma unroll
            for (int r = 0; r < 4; r++) acc[i][j][r] = 0.f;

    for (int k0 = 0; k0 < KD; k0 += G1_BK) {
#pragma unroll
        for (int i = 0; i < 4; i++) {
            int f  = tid + i * 256;
            int r  = f >> 3;
            int kq = f & 7;
            float4 v = make_float4(0.f, 0.f, 0.f, 0.f);
            int rg = row0 + r;
            if (rg < NN)
                v = *reinterpret_cast<const float4*>(X + (size_t)rg * KD + k0 + kq * 4);
            v.x = to_tf32(v.x); v.y = to_tf32(v.y);
            v.z = to_tf32(v.z); v.w = to_tf32(v.w);
            *reinterpret_cast<float4*>(&As[r][kq * 4]) = v;
        }
#pragma unroll
        for (int i = 0; i < 4; i++) {
            int f  = tid + i * 256;
            int c  = f >> 3;
            int kq = f & 7;
            float4 v = *reinterpret_cast<const float4*>(Wd + (size_t)c * KD + k0 + kq * 4);
            v.x = to_tf32(v.x); v.y = to_tf32(v.y);
            v.z = to_tf32(v.z); v.w = to_tf32(v.w);
            *reinterpret_cast<float4*>(&Bs[c][kq * 4]) = v;
        }
        __syncthreads();
#pragma unroll
        for (int ks = 0; ks < 4; ks++) {
            const int kb = ks * 8;
            uint32_t af[4][4];
#pragma unroll
            for (int mt = 0; mt < 4; mt++) {
                int ra = wm * 64 + mt * 16 + g;
                af[mt][0] = __float_as_uint(As[ra][kb + tig]);
                af[mt][1] = __float_as_uint(As[ra + 8][kb + tig]);
                af[mt][2] = __float_as_uint(As[ra][kb + tig + 4]);
                af[mt][3] = __float_as_uint(As[ra + 8][kb + tig + 4]);
            }
            uint32_t bf[4][2];
#pragma unroll
            for (int nt = 0; nt < 4; nt++) {
                int nb = wn * 32 + nt * 8 + g;
                bf[nt][0] = __float_as_uint(Bs[nb][kb + tig]);
                bf[nt][1] = __float_as_uint(Bs[nb][kb + tig + 4]);
            }
#pragma unroll
            for (int mt = 0; mt < 4; mt++)
#pragma unroll
                for (int nt = 0; nt < 4; nt++) {
                    asm volatile(
                        "mma.sync.aligned.m16n8k8.row.col.f32.tf32.tf32.f32 "
                        "{%0,%1,%2,%3}, {%4,%5,%6,%7}, {%8,%9}, {%0,%1,%2,%3};"
                        : "+f"(acc[mt][nt][0]), "+f"(acc[mt][nt][1]),
                          "+f"(acc[mt][nt][2]), "+f"(acc[mt][nt][3])
                        : "r"(af[mt][0]), "r"(af[mt][1]), "r"(af[mt][2]), "r"(af[mt][3]),
                          "r"(bf[nt][0]), "r"(bf[nt][1]));
                }
        }
        __syncthreads();
    }
#pragma unroll
    for (int mt = 0; mt < 4; mt++) {
#pragma unroll
        for (int half = 0; half < 2; half++) {
            int r = row0 + wm * 64 + mt * 16 + g + half * 8;
            if (r >= NN) continue;
#pragma unroll
            for (int nt = 0; nt < 4; nt++) {
                int c = wn * 32 + nt * 8 + tig * 2;
                float v0 = acc[mt][nt][half * 2]     + __ldg(bd + c);
                float v1 = acc[mt][nt][half * 2 + 1] + __ldg(bd + c + 1);
                v0 = v0 > 0.f ? v0 : 0.01f * v0;
                v1 = v1 > 0.f ? v1 : 0.01f * v1;
                *reinterpret_cast<float2*>(g_h + (size_t)r * EM + c) = make_float2(v0, v1);
            }
        }
    }
}

// ---------------- GEMM2 + attention logits ----------------
#define RPB 128
__global__ __launch_bounds__(256) void k_gemm2(const float* __restrict__ Wg,
                                               const float* __restrict__ att_s,
                                               const float* __restrict__ att_d) {
    __shared__ float Wgs[OD][EM + 4];
    __shared__ float hs[4][EM];
    __shared__ float red_s[4][2], red_d[4][2];
    __shared__ float ats[OD], atd[OD];
    const int tid = threadIdx.x;
    const int tx = tid & 63;
    const int ty = tid >> 6;

#pragma unroll
    for (int i = 0; i < 8; i++) {
        int f = tid + i * 256;
        int c = f >> 5;
        int kq = f & 31;
        float4 v = *reinterpret_cast<const float4*>(Wg + (size_t)c * EM + kq * 4);
        *reinterpret_cast<float4*>(&Wgs[c][kq * 4]) = v;
    }
    if (tid < OD) { ats[tid] = att_s[tid]; atd[tid] = att_d[tid]; }

    const int base = blockIdx.x * RPB;
    for (int rg = 0; rg < RPB; rg += 4) {
        __syncthreads();
        if (tid < 128) {
            int r = tid >> 5;
            int kq = tid & 31;
            int row = base + rg + r;
            float4 v = make_float4(0.f, 0.f, 0.f, 0.f);
            if (row < NN)
                v = *reinterpret_cast<const float4*>(g_h + (size_t)row * EM + kq * 4);
            *reinterpret_cast<float4*>(&hs[r][kq * 4]) = v;
        }
        __syncthreads();
        int row = base + rg + ty;
        float acc = 0.f;
#pragma unroll
        for (int k = 0; k < EM; k += 4) {
            float4 w  = *reinterpret_cast<const float4*>(&Wgs[tx][k]);
            float4 h4 = *reinterpret_cast<const float4*>(&hs[ty][k]);
            acc = fmaf(w.x, h4.x, acc);
            acc = fmaf(w.y, h4.y, acc);
            acc = fmaf(w.z, h4.z, acc);
            acc = fmaf(w.w, h4.w, acc);
        }
        if (row < NN) g_g[(size_t)row * OD + tx] = acc;

        float ps = acc * ats[tx];
        float pd = acc * atd[tx];
#pragma unroll
        for (int off = 16; off > 0; off >>= 1) {
            ps += __shfl_xor_sync(0xffffffffu, ps, off);
            pd += __shfl_xor_sync(0xffffffffu, pd, off);
        }
        int half = tx >> 5;
        if ((tx & 31) == 0) { red_s[ty][half] = ps; red_d[ty][half] = pd; }
        __syncthreads();
        if (tx == 0 && row < NN) {
            g_as[row] = red_s[ty][0] + red_s[ty][1];
            g_ad[row] = red_d[ty][0] + red_d[ty][1];
        }
    }
}

// ---------------- fused softmax + gather accumulate (warp per dst, no atomics) ----------------
// 32-edge batches: every lane computes its own edge weight (expf issued once per
// 32 edges per warp), den accumulated lane-locally, gathers pipelined (MLP up to 32).
__global__ __launch_bounds__(256) void k_accum(float* __restrict__ out,
                                               const float* __restrict__ bg) {
    const unsigned FULL = 0xffffffffu;
    int w    = (blockIdx.x * blockDim.x + threadIdx.x) >> 5;
    int lane = threadIdx.x & 31;
    if (w >= NN) return;
    int beg = g_off[w];
    int cnt = g_cnt[w];
    float a_d = g_ad[w];

    // self loop
    float e0 = g_as[w] + a_d;
    e0 = e0 > 0.f ? e0 : 0.2f * e0;
    float wt_self = __expf(e0);
    float2 gw = *reinterpret_cast<const float2*>(g_g + (size_t)w * OD + lane * 2);
    float acc0 = wt_self * gw.x, acc1 = wt_self * gw.y;

    float den_l = 0.f;
    int end = beg + cnt;
    for (int j = beg; j < end; j += 32) {
        int m = end - j;
        if (m > 32) m = 32;
        int   s_l  = w;
        float wt_l = 0.f;
        if (lane < m) {
            s_l = g_esrc[j + lane];
            float e = g_as[s_l] + a_d;
            e = e > 0.f ? e : 0.2f * e;
            wt_l = __expf(e);
        }
        den_l += wt_l;
        if (m == 32) {
#pragma unroll 8
            for (int u = 0; u < 32; u++) {
                int   s  = __shfl_sync(FULL, s_l, u);
                float wt = __shfl_sync(FULL, wt_l, u);
                float2 gv = *reinterpret_cast<const float2*>(g_g + (size_t)s * OD + lane * 2);
                acc0 = fmaf(wt, gv.x, acc0);
                acc1 = fmaf(wt, gv.y, acc1);
            }
        } else {
            for (int u = 0; u < m; u++) {
                int   s  = __shfl_sync(FULL, s_l, u);
                float wt = __shfl_sync(FULL, wt_l, u);
                float2 gv = *reinterpret_cast<const float2*>(g_g + (size_t)s * OD + lane * 2);
                acc0 = fmaf(wt, gv.x, acc0);
                acc1 = fmaf(wt, gv.y, acc1);
            }
        }
    }
    // reduce den across lanes, add self
#pragma unroll
    for (int o = 16; o > 0; o >>= 1)
        den_l += __shfl_xor_sync(FULL, den_l, o);
    float inv = 1.f / (den_l + wt_self);
    int c = lane * 2;
    float2 b2 = *reinterpret_cast<const float2*>(bg + c);
    *reinterpret_cast<float2*>(out + (size_t)w * OD + c) =
        make_float2(acc0 * inv + b2.x, acc1 * inv + b2.y);
}

// ---------------- launch ----------------
extern "C" void kernel_launch(void* const* d_in, const int* in_sizes, int n_in,
                              void* d_out, int out_size) {
    const float* x   = (const float*)d_in[0];
    const int*   ei  = (const int*)  d_in[1];
    const float* Wd  = (const float*)d_in[2];
    const float* bd  = (const float*)d_in[3];
    const float* Wg  = (const float*)d_in[4];
    const float* ats = (const float*)d_in[5];
    const float* atd = (const float*)d_in[6];
    const float* bg  = (const float*)d_in[7];
    float* out = (float*)d_out;

    const int E = in_sizes[1] / 2;

    // lazy one-time resources (created outside capture on the correctness run)
    static cudaStream_t s2 = nullptr;
    static cudaEvent_t ev_fork = nullptr, ev_join = nullptr;
    if (!s2) {
        cudaStreamCreate(&s2);
        cudaEventCreateWithFlags(&ev_fork, cudaEventDisableTiming);
        cudaEventCreateWithFlags(&ev_join, cudaEventDisableTiming);
    }

    // fork: CSR build on s2, GEMMs on origin stream
    cudaEventRecord(ev_fork, 0);
    cudaStreamWaitEvent(s2, ev_fork, 0);

    k_zero<<<(NN + 255) / 256, 256, 0, s2>>>();
    k_hist<<<(E + 255) / 256, 256, 0, s2>>>(ei, E);
    k_scan1<<<SCAN_B, 256, 0, s2>>>();
    k_scan2<<<1, 256, 0, s2>>>();
    k_scan3<<<SCAN_B, 256, 0, s2>>>();
    k_scatter<<<(E + 255) / 256, 256, 0, s2>>>(ei, E);
    cudaEventRecord(ev_join, s2);

    k_gemm1<<<(NN + G1_BM - 1) / G1_BM, 256>>>(x, Wd, bd);
    k_gemm2<<<(NN + RPB - 1) / RPB, 256>>>(Wg, ats, atd);

    // join, then fused softmax-gather-normalize
    cudaStreamWaitEvent(0, ev_join, 0);
    k_accum<<<(NN * 32 + 255) / 256, 256>>>(out, bg);
}

// round 8
// speedup vs baseline: 2.8649x; 1.1878x over previous
#include <cuda_runtime.h>
#include <cstdint>

#define NN 50000
#define KD 512
#define EM 128
#define OD 64
#define EE 1600000
#define SCAN_B 196            // 196 * 256 = 50176 >= NN

// ---------------- scratch (device globals) ----------------
__device__ float g_h[(size_t)NN * EM];
__device__ float g_g[(size_t)NN * OD];
__device__ float g_as[NN];
__device__ float g_ad[NN];
__device__ int   g_cnt[NN];
__device__ int   g_off[NN];
__device__ int   g_pos[NN];
__device__ int   g_esrc[EE];
__device__ int   g_bsum[SCAN_B];
__device__ int   g_boff[SCAN_B];

__device__ __forceinline__ float to_tf32(float x) {
    float r;
    asm("cvt.rna.tf32.f32 %0, %1;" : "=f"(r) : "f"(x));
    return r;
}

// ---------------- CSR build ----------------
__global__ void k_zero() {
    int i = blockIdx.x * blockDim.x + threadIdx.x;
    if (i < NN) g_cnt[i] = 0;
}

__global__ void k_hist(const int* __restrict__ ei, int E) {
    int i = blockIdx.x * blockDim.x + threadIdx.x;
    if (i < E) atomicAdd(g_cnt + ei[E + i], 1);
}

__global__ __launch_bounds__(256) void k_scan1() {
    __shared__ int sh[256];
    int t = threadIdx.x;
    int i = blockIdx.x * 256 + t;
    int v = (i < NN) ? g_cnt[i] : 0;
    sh[t] = v;
    __syncthreads();
#pragma unroll
    for (int o = 128; o > 0; o >>= 1) {
        if (t < o) sh[t] += sh[t + o];
        __syncthreads();
    }
    if (t == 0) g_bsum[blockIdx.x] = sh[0];
}

__global__ __launch_bounds__(256) void k_scan2() {
    __shared__ int sh[256];
    int t = threadIdx.x;
    int v = (t < SCAN_B) ? g_bsum[t] : 0;
    sh[t] = v;
    __syncthreads();
#pragma unroll
    for (int o = 1; o < 256; o <<= 1) {
        int u = (t >= o) ? sh[t - o] : 0;
        __syncthreads();
        sh[t] += u;
        __syncthreads();
    }
    if (t < SCAN_B) g_boff[t] = sh[t] - v;
}

__global__ __launch_bounds__(256) void k_scan3() {
    __shared__ int sh[256];
    int t = threadIdx.x;
    int i = blockIdx.x * 256 + t;
    int v = (i < NN) ? g_cnt[i] : 0;
    sh[t] = v;
    __syncthreads();
#pragma unroll
    for (int o = 1; o < 256; o <<= 1) {
        int u = (t >= o) ? sh[t - o] : 0;
        __syncthreads();
        sh[t] += u;
        __syncthreads();
    }
    if (i < NN) {
        int off = g_boff[blockIdx.x] + sh[t] - v;
        g_off[i] = off;
        g_pos[i] = off;
    }
}

__global__ void k_scatter(const int* __restrict__ ei, int E) {
    int i = blockIdx.x * blockDim.x + threadIdx.x;
    if (i >= E) return;
    int s = ei[i];
    int d = ei[E + i];
    int p = atomicAdd(g_pos + d, 1);
    g_esrc[p] = s;
}

// ---------------- GEMM1 (tensor cores, tf32 mma.m16n8k8) ----------------
#define G1_BM 128
#define G1_BK 32
#define G1_LDS (G1_BK + 4)
__global__ __launch_bounds__(256) void k_gemm1(const float* __restrict__ X,
                                               const float* __restrict__ Wd,
                                               const float* __restrict__ bd) {
    __shared__ float As[G1_BM][G1_LDS];
    __shared__ float Bs[EM][G1_LDS];
    const int tid  = threadIdx.x;
    const int warp = tid >> 5;
    const int lane = tid & 31;
    const int g    = lane >> 2;
    const int tig  = lane & 3;
    const int wm   = warp >> 2;
    const int wn   = warp & 3;
    const int row0 = blockIdx.x * G1_BM;

    float acc[4][4][4];
#pragma unroll
    for (int i = 0; i < 4; i++)
#pragma unroll
        for (int j = 0; j < 4; j++)
#pragma unroll
            for (int r = 0; r < 4; r++) acc[i][j][r] = 0.f;

    for (int k0 = 0; k0 < KD; k0 += G1_BK) {
#pragma unroll
        for (int i = 0; i < 4; i++) {
            int f  = tid + i * 256;
            int r  = f >> 3;
            int kq = f & 7;
            float4 v = make_float4(0.f, 0.f, 0.f, 0.f);
            int rg = row0 + r;
            if (rg < NN)
                v = *reinterpret_cast<const float4*>(X + (size_t)rg * KD + k0 + kq * 4);
            v.x = to_tf32(v.x); v.y = to_tf32(v.y);
            v.z = to_tf32(v.z); v.w = to_tf32(v.w);
            *reinterpret_cast<float4*>(&As[r][kq * 4]) = v;
        }
#pragma unroll
        for (int i = 0; i < 4; i++) {
            int f  = tid + i * 256;
            int c  = f >> 3;
            int kq = f & 7;
            float4 v = *reinterpret_cast<const float4*>(Wd + (size_t)c * KD + k0 + kq * 4);
            v.x = to_tf32(v.x); v.y = to_tf32(v.y);
            v.z = to_tf32(v.z); v.w = to_tf32(v.w);
            *reinterpret_cast<float4*>(&Bs[c][kq * 4]) = v;
        }
        __syncthreads();
#pragma unroll
        for (int ks = 0; ks < 4; ks++) {
            const int kb = ks * 8;
            uint32_t af[4][4];
#pragma unroll
            for (int mt = 0; mt < 4; mt++) {
                int ra = wm * 64 + mt * 16 + g;
                af[mt][0] = __float_as_uint(As[ra][kb + tig]);
                af[mt][1] = __float_as_uint(As[ra + 8][kb + tig]);
                af[mt][2] = __float_as_uint(As[ra][kb + tig + 4]);
                af[mt][3] = __float_as_uint(As[ra + 8][kb + tig + 4]);
            }
            uint32_t bf[4][2];
#pragma unroll
            for (int nt = 0; nt < 4; nt++) {
                int nb = wn * 32 + nt * 8 + g;
                bf[nt][0] = __float_as_uint(Bs[nb][kb + tig]);
                bf[nt][1] = __float_as_uint(Bs[nb][kb + tig + 4]);
            }
#pragma unroll
            for (int mt = 0; mt < 4; mt++)
#pragma unroll
                for (int nt = 0; nt < 4; nt++) {
                    asm volatile(
                        "mma.sync.aligned.m16n8k8.row.col.f32.tf32.tf32.f32 "
                        "{%0,%1,%2,%3}, {%4,%5,%6,%7}, {%8,%9}, {%0,%1,%2,%3};"
                        : "+f"(acc[mt][nt][0]), "+f"(acc[mt][nt][1]),
                          "+f"(acc[mt][nt][2]), "+f"(acc[mt][nt][3])
                        : "r"(af[mt][0]), "r"(af[mt][1]), "r"(af[mt][2]), "r"(af[mt][3]),
                          "r"(bf[nt][0]), "r"(bf[nt][1]));
                }
        }
        __syncthreads();
    }
#pragma unroll
    for (int mt = 0; mt < 4; mt++) {
#pragma unroll
        for (int half = 0; half < 2; half++) {
            int r = row0 + wm * 64 + mt * 16 + g + half * 8;
            if (r >= NN) continue;
#pragma unroll
            for (int nt = 0; nt < 4; nt++) {
                int c = wn * 32 + nt * 8 + tig * 2;
                float v0 = acc[mt][nt][half * 2]     + __ldg(bd + c);
                float v1 = acc[mt][nt][half * 2 + 1] + __ldg(bd + c + 1);
                v0 = v0 > 0.f ? v0 : 0.01f * v0;
                v1 = v1 > 0.f ? v1 : 0.01f * v1;
                *reinterpret_cast<float2*>(g_h + (size_t)r * EM + c) = make_float2(v0, v1);
            }
        }
    }
}

// ---------------- GEMM2 (tensor cores) + attention logits ----------------
// g = h @ Wg^T : [NN,128] x [64,128]^T -> [NN,64]; also a_src = g@ats, a_dst = g@atd.
// Block tile 128 rows x 64 cols, K=128 in 4 chunks of 32.
// 8 warps: 4 (M) x 2 (N); warp tile 32x32 -> 2 m-tiles x 4 n-tiles of m16n8k8.
#define G2_BM 128
#define G2_LDS 36
__global__ __launch_bounds__(256) void k_gemm2(const float* __restrict__ Wg,
                                               const float* __restrict__ att_s,
                                               const float* __restrict__ att_d) {
    __shared__ float As[G2_BM][G2_LDS];
    __shared__ float Bs[OD][G2_LDS];
    __shared__ float ps_sh[G2_BM][2], pd_sh[G2_BM][2];
    __shared__ float ats[OD], atd[OD];
    const int tid  = threadIdx.x;
    const int warp = tid >> 5;
    const int lane = tid & 31;
    const int g    = lane >> 2;
    const int tig  = lane & 3;
    const int wm   = warp >> 1;        // 0..3 -> rows wm*32
    const int wn   = warp & 1;         // 0..1 -> cols wn*32
    const int row0 = blockIdx.x * G2_BM;

    if (tid < OD) { ats[tid] = att_s[tid]; atd[tid] = att_d[tid]; }

    float acc[2][4][4];
#pragma unroll
    for (int i = 0; i < 2; i++)
#pragma unroll
        for (int j = 0; j < 4; j++)
#pragma unroll
            for (int r = 0; r < 4; r++) acc[i][j][r] = 0.f;

    for (int k0 = 0; k0 < EM; k0 += 32) {
#pragma unroll
        for (int i = 0; i < 4; i++) {
            int f  = tid + i * 256;
            int r  = f >> 3;
            int kq = f & 7;
            float4 v = make_float4(0.f, 0.f, 0.f, 0.f);
            int rg = row0 + r;
            if (rg < NN)
                v = *reinterpret_cast<const float4*>(g_h + (size_t)rg * EM + k0 + kq * 4);
            v.x = to_tf32(v.x); v.y = to_tf32(v.y);
            v.z = to_tf32(v.z); v.w = to_tf32(v.w);
            *reinterpret_cast<float4*>(&As[r][kq * 4]) = v;
        }
#pragma unroll
        for (int i = 0; i < 2; i++) {
            int f  = tid + i * 256;
            int c  = f >> 3;
            int kq = f & 7;
            float4 v = *reinterpret_cast<const float4*>(Wg + (size_t)c * EM + k0 + kq * 4);
            v.x = to_tf32(v.x); v.y = to_tf32(v.y);
            v.z = to_tf32(v.z); v.w = to_tf32(v.w);
            *reinterpret_cast<float4*>(&Bs[c][kq * 4]) = v;
        }
        __syncthreads();
#pragma unroll
        for (int ks = 0; ks < 4; ks++) {
            const int kb = ks * 8;
            uint32_t af[2][4];
#pragma unroll
            for (int mt = 0; mt < 2; mt++) {
                int ra = wm * 32 + mt * 16 + g;
                af[mt][0] = __float_as_uint(As[ra][kb + tig]);
                af[mt][1] = __float_as_uint(As[ra + 8][kb + tig]);
                af[mt][2] = __float_as_uint(As[ra][kb + tig + 4]);
                af[mt][3] = __float_as_uint(As[ra + 8][kb + tig + 4]);
            }
            uint32_t bf[4][2];
#pragma unroll
            for (int nt = 0; nt < 4; nt++) {
                int nb = wn * 32 + nt * 8 + g;
                bf[nt][0] = __float_as_uint(Bs[nb][kb + tig]);
                bf[nt][1] = __float_as_uint(Bs[nb][kb + tig + 4]);
            }
#pragma unroll
            for (int mt = 0; mt < 2; mt++)
#pragma unroll
                for (int nt = 0; nt < 4; nt++) {
                    asm volatile(
                        "mma.sync.aligned.m16n8k8.row.col.f32.tf32.tf32.f32 "
                        "{%0,%1,%2,%3}, {%4,%5,%6,%7}, {%8,%9}, {%0,%1,%2,%3};"
                        : "+f"(acc[mt][nt][0]), "+f"(acc[mt][nt][1]),
                          "+f"(acc[mt][nt][2]), "+f"(acc[mt][nt][3])
                        : "r"(af[mt][0]), "r"(af[mt][1]), "r"(af[mt][2]), "r"(af[mt][3]),
                          "r"(bf[nt][0]), "r"(bf[nt][1]));
                }
        }
        __syncthreads();
    }

    // epilogue: store g, compute per-row partial logits over this warp's 32 cols
#pragma unroll
    for (int mt = 0; mt < 2; mt++) {
#pragma unroll
        for (int half = 0; half < 2; half++) {
            int rloc = wm * 32 + mt * 16 + g + half * 8;
            int r = row0 + rloc;
            float ps = 0.f, pd = 0.f;
#pragma unroll
            for (int nt = 0; nt < 4; nt++) {
                int c = wn * 32 + nt * 8 + tig * 2;
                float v0 = acc[mt][nt][half * 2];
                float v1 = acc[mt][nt][half * 2 + 1];
                if (r < NN)
                    *reinterpret_cast<float2*>(g_g + (size_t)r * OD + c) = make_float2(v0, v1);
                ps = fmaf(v0, ats[c], fmaf(v1, ats[c + 1], ps));
                pd = fmaf(v0, atd[c], fmaf(v1, atd[c + 1], pd));
            }
            // reduce over tig (lane bits 0..1)
            ps += __shfl_xor_sync(0xffffffffu, ps, 1);
            ps += __shfl_xor_sync(0xffffffffu, ps, 2);
            pd += __shfl_xor_sync(0xffffffffu, pd, 1);
            pd += __shfl_xor_sync(0xffffffffu, pd, 2);
            if (tig == 0) { ps_sh[rloc][wn] = ps; pd_sh[rloc][wn] = pd; }
        }
    }
    __syncthreads();
    if (tid < G2_BM) {
        int r = row0 + tid;
        if (r < NN) {
            g_as[r] = ps_sh[tid][0] + ps_sh[tid][1];
            g_ad[r] = pd_sh[tid][0] + pd_sh[tid][1];
        }
    }
}

// ---------------- fused softmax + gather accumulate ----------------
// 2 warps per dst (32 cols each). 32-edge batches, always-staged 32-deep gather
// (pad lanes gather the dst row with wt=0 -> L1 hits, no serial tail).
__global__ __launch_bounds__(256) void k_accum(float* __restrict__ out,
                                               const float* __restrict__ bg) {
    const unsigned FULL = 0xffffffffu;
    int W    = (blockIdx.x * blockDim.x + threadIdx.x) >> 5;
    int lane = threadIdx.x & 31;
    int dst  = W >> 1;
    int half = W & 1;
    if (dst >= NN) return;
    int col = half * 32 + lane;
    int beg = g_off[dst];
    int cnt = g_cnt[dst];
    float a_d = g_ad[dst];

    // self loop
    float e0 = g_as[dst] + a_d;
    e0 = e0 > 0.f ? e0 : 0.2f * e0;
    float wt_self = __expf(e0);
    float acc = wt_self * g_g[(size_t)dst * OD + col];
    float den_l = (lane == 0) ? wt_self : 0.f;

    int end = beg + cnt;
    for (int j = beg; j < end; j += 32) {
        int m = end - j;
        if (m > 32) m = 32;
        int   s_l  = dst;
        float wt_l = 0.f;
        if (lane < m) {
            s_l = g_esrc[j + lane];
            float e = g_as[s_l] + a_d;
            e = e > 0.f ? e : 0.2f * e;
            wt_l = __expf(e);
        }
        den_l += wt_l;
        float gvs[32];
#pragma unroll
        for (int u = 0; u < 32; u++) {
            int s = __shfl_sync(FULL, s_l, u);
            gvs[u] = g_g[(size_t)s * OD + col];
        }
#pragma unroll
        for (int u = 0; u < 32; u++) {
            float wt = __shfl_sync(FULL, wt_l, u);
            acc = fmaf(wt, gvs[u], acc);
        }
    }
#pragma unroll
    for (int o = 16; o > 0; o >>= 1)
        den_l += __shfl_xor_sync(FULL, den_l, o);
    out[(size_t)dst * OD + col] = acc / den_l + __ldg(bg + col);
}

// ---------------- launch ----------------
extern "C" void kernel_launch(void* const* d_in, const int* in_sizes, int n_in,
                              void* d_out, int out_size) {
    const float* x   = (const float*)d_in[0];
    const int*   ei  = (const int*)  d_in[1];
    const float* Wd  = (const float*)d_in[2];
    const float* bd  = (const float*)d_in[3];
    const float* Wg  = (const float*)d_in[4];
    const float* ats = (const float*)d_in[5];
    const float* atd = (const float*)d_in[6];
    const float* bg  = (const float*)d_in[7];
    float* out = (float*)d_out;

    const int E = in_sizes[1] / 2;

    static cudaStream_t s2 = nullptr;
    static cudaEvent_t ev_fork = nullptr, ev_join = nullptr;
    if (!s2) {
        cudaStreamCreate(&s2);
        cudaEventCreateWithFlags(&ev_fork, cudaEventDisableTiming);
        cudaEventCreateWithFlags(&ev_join, cudaEventDisableTiming);
    }

    cudaEventRecord(ev_fork, 0);
    cudaStreamWaitEvent(s2, ev_fork, 0);

    k_zero<<<(NN + 255) / 256, 256, 0, s2>>>();
    k_hist<<<(E + 255) / 256, 256, 0, s2>>>(ei, E);
    k_scan1<<<SCAN_B, 256, 0, s2>>>();
    k_scan2<<<1, 256, 0, s2>>>();
    k_scan3<<<SCAN_B, 256, 0, s2>>>();
    k_scatter<<<(E + 255) / 256, 256, 0, s2>>>(ei, E);
    cudaEventRecord(ev_join, s2);

    k_gemm1<<<(NN + G1_BM - 1) / G1_BM, 256>>>(x, Wd, bd);
    k_gemm2<<<(NN + G2_BM - 1) / G2_BM, 256>>>(Wg, ats, atd);

    cudaStreamWaitEvent(0, ev_join, 0);
    {
        long long warps = (long long)NN * 2;
        int blocks = (int)((warps * 32 + 255) / 256);
        k_accum<<<blocks, 256>>>(out, bg);
    }
}